// round 2
// baseline (speedup 1.0000x reference)
#include <cuda_runtime.h>
#include <stdint.h>

// Problem constants (fixed shapes from the reference)
#define D      1024
#define LSEQ   8192
#define NBATCH 4
#define NSAMP  2048
#define NROWS  (NBATCH * NSAMP)   // 8192 sampled rows
#define MROWS  (NBATCH * LSEQ)    // 32768 output rows
#define KSPLIT 8
#define KCHUNK (NROWS / KSPLIT)   // 1024

// SGEMM tiling: 128x128 tile, BK=8, 256 threads, 8x8 accum per thread
#define BM 128
#define BN 128
#define BK 8

// Device-global scratch (no allocations allowed in kernel_launch)
__device__ float g_M[(size_t)D * D];                 // W @ decorr            (4 MB)
__device__ float g_xs[(size_t)NROWS * D];            // gathered @ decorr^T   (32 MB)
__device__ float g_Gp[(size_t)KSPLIT * D * D];       // split-K partials of G (32 MB)
__device__ float g_row_r[NROWS];
__device__ float g_row_q[NROWS];

__device__ __forceinline__ void mma_tile(const float (&As)[BK][BM],
                                         const float (&Bs)[BK][BN],
                                         float (&acc)[8][8], int tx, int ty) {
#pragma unroll
    for (int kk = 0; kk < BK; kk++) {
        float a[8], b[8];
        *(float4*)&a[0] = *(const float4*)&As[kk][tx * 4];
        *(float4*)&a[4] = *(const float4*)&As[kk][64 + tx * 4];
        *(float4*)&b[0] = *(const float4*)&Bs[kk][ty * 4];
        *(float4*)&b[4] = *(const float4*)&Bs[kk][64 + ty * 4];
#pragma unroll
        for (int i = 0; i < 8; i++)
#pragma unroll
            for (int j = 0; j < 8; j++)
                acc[i][j] += a[i] * b[j];
    }
}

// ---------------------------------------------------------------------------
// K1: g_M = W @ decorr          (NN, 1024^3)
// ---------------------------------------------------------------------------
__global__ __launch_bounds__(256) void k_prep_M(const float* __restrict__ W,
                                                const float* __restrict__ dec) {
    __shared__ float As[BK][BM];
    __shared__ float Bs[BK][BN];
    const int tid = threadIdx.x;
    const int m0 = blockIdx.y * BM, n0 = blockIdx.x * BN;
    const int tx = tid & 15, ty = tid >> 4;
    const int ar = tid >> 1, ac = (tid & 1) * 4;   // A loader: 128 rows x 2 float4
    const int br = tid >> 5, bc = (tid & 31) * 4;  // B loader: 8 rows x 32 float4
    float acc[8][8] = {};
    for (int k0 = 0; k0 < D; k0 += BK) {
        float4 av = *(const float4*)&W[(size_t)(m0 + ar) * D + k0 + ac];
        As[ac + 0][ar] = av.x; As[ac + 1][ar] = av.y;
        As[ac + 2][ar] = av.z; As[ac + 3][ar] = av.w;
        *(float4*)&Bs[br][bc] = *(const float4*)&dec[(size_t)(k0 + br) * D + n0 + bc];
        __syncthreads();
        mma_tile(As, Bs, acc, tx, ty);
        __syncthreads();
    }
#pragma unroll
    for (int i = 0; i < 8; i++) {
        int m = m0 + (i < 4 ? tx * 4 + i : 64 + tx * 4 + (i - 4));
        *(float4*)&g_M[(size_t)m * D + n0 + ty * 4] =
            make_float4(acc[i][0], acc[i][1], acc[i][2], acc[i][3]);
        *(float4*)&g_M[(size_t)m * D + n0 + 64 + ty * 4] =
            make_float4(acc[i][4], acc[i][5], acc[i][6], acc[i][7]);
    }
}

// ---------------------------------------------------------------------------
// K2: y = x @ g_M^T + bias      (NT, 32768x1024x1024)
// ---------------------------------------------------------------------------
__global__ __launch_bounds__(256) void k_y(const float* __restrict__ x,
                                           const float* __restrict__ bias,
                                           float* __restrict__ y) {
    __shared__ float As[BK][BM];
    __shared__ float Bs[BK][BN];
    const int tid = threadIdx.x;
    const int m0 = blockIdx.y * BM, n0 = blockIdx.x * BN;
    const int tx = tid & 15, ty = tid >> 4;
    const int lr = tid >> 1, lc = (tid & 1) * 4;
    float acc[8][8] = {};
    const float* arow = x + (size_t)(m0 + lr) * D + lc;
    const float* brow = g_M + (size_t)(n0 + lr) * D + lc;
    for (int k0 = 0; k0 < D; k0 += BK) {
        float4 av = *(const float4*)(arow + k0);
        float4 bv = *(const float4*)(brow + k0);
        As[lc + 0][lr] = av.x; As[lc + 1][lr] = av.y;
        As[lc + 2][lr] = av.z; As[lc + 3][lr] = av.w;
        Bs[lc + 0][lr] = bv.x; Bs[lc + 1][lr] = bv.y;
        Bs[lc + 2][lr] = bv.z; Bs[lc + 3][lr] = bv.w;
        __syncthreads();
        mma_tile(As, Bs, acc, tx, ty);
        __syncthreads();
    }
    float4 blo = *(const float4*)&bias[n0 + ty * 4];
    float4 bhi = *(const float4*)&bias[n0 + 64 + ty * 4];
#pragma unroll
    for (int i = 0; i < 8; i++) {
        int m = m0 + (i < 4 ? tx * 4 + i : 64 + tx * 4 + (i - 4));
        *(float4*)&y[(size_t)m * D + n0 + ty * 4] =
            make_float4(acc[i][0] + blo.x, acc[i][1] + blo.y,
                        acc[i][2] + blo.z, acc[i][3] + blo.w);
        *(float4*)&y[(size_t)m * D + n0 + 64 + ty * 4] =
            make_float4(acc[i][4] + bhi.x, acc[i][5] + bhi.y,
                        acc[i][6] + bhi.z, acc[i][7] + bhi.w);
    }
}

// ---------------------------------------------------------------------------
// K3: g_xs = gather(x, sample_idx) @ decorr^T   (NT with row gather, 8192x1024x1024)
// ---------------------------------------------------------------------------
__global__ __launch_bounds__(256) void k_xs(const float* __restrict__ x,
                                            const float* __restrict__ dec,
                                            const int* __restrict__ sidx) {
    __shared__ float As[BK][BM];
    __shared__ float Bs[BK][BN];
    const int tid = threadIdx.x;
    const int m0 = blockIdx.y * BM, n0 = blockIdx.x * BN;
    const int tx = tid & 15, ty = tid >> 4;
    const int lr = tid >> 1, lc = (tid & 1) * 4;
    float acc[8][8] = {};
    const int gr = m0 + lr;              // global sample row
    const int bidx = gr >> 11;           // / NSAMP
    const int tok = sidx[gr];            // token index in [0, LSEQ)
    const float* arow = x + ((size_t)bidx * LSEQ + (size_t)tok) * D + lc;
    const float* brow = dec + (size_t)(n0 + lr) * D + lc;
    for (int k0 = 0; k0 < D; k0 += BK) {
        float4 av = *(const float4*)(arow + k0);
        float4 bv = *(const float4*)(brow + k0);
        As[lc + 0][lr] = av.x; As[lc + 1][lr] = av.y;
        As[lc + 2][lr] = av.z; As[lc + 3][lr] = av.w;
        Bs[lc + 0][lr] = bv.x; Bs[lc + 1][lr] = bv.y;
        Bs[lc + 2][lr] = bv.z; Bs[lc + 3][lr] = bv.w;
        __syncthreads();
        mma_tile(As, Bs, acc, tx, ty);
        __syncthreads();
    }
#pragma unroll
    for (int i = 0; i < 8; i++) {
        int m = m0 + (i < 4 ? tx * 4 + i : 64 + tx * 4 + (i - 4));
        *(float4*)&g_xs[(size_t)m * D + n0 + ty * 4] =
            make_float4(acc[i][0], acc[i][1], acc[i][2], acc[i][3]);
        *(float4*)&g_xs[(size_t)m * D + n0 + 64 + ty * 4] =
            make_float4(acc[i][4], acc[i][5], acc[i][6], acc[i][7]);
    }
}

// ---------------------------------------------------------------------------
// K4: split-K partials of G = xs^T @ xs  (TN, 1024x1024xKCHUNK per z-slice)
// ---------------------------------------------------------------------------
__global__ __launch_bounds__(256) void k_syrk_part() {
    __shared__ float As[BK][BM];
    __shared__ float Bs[BK][BN];
    const int tid = threadIdx.x;
    const int i0 = blockIdx.y * BM, j0 = blockIdx.x * BN;
    const int tx = tid & 15, ty = tid >> 4;
    const int lr = tid >> 5, lc = (tid & 31) * 4;  // 8 xs-rows x 32 float4
    float acc[8][8] = {};
    const int kbeg = blockIdx.z * KCHUNK;
    for (int k0 = kbeg; k0 < kbeg + KCHUNK; k0 += BK) {
        *(float4*)&As[lr][lc] = *(const float4*)&g_xs[(size_t)(k0 + lr) * D + i0 + lc];
        *(float4*)&Bs[lr][lc] = *(const float4*)&g_xs[(size_t)(k0 + lr) * D + j0 + lc];
        __syncthreads();
        mma_tile(As, Bs, acc, tx, ty);
        __syncthreads();
    }
    float* Cp = g_Gp + (size_t)blockIdx.z * D * D;
#pragma unroll
    for (int i = 0; i < 8; i++) {
        int m = i0 + (i < 4 ? tx * 4 + i : 64 + tx * 4 + (i - 4));
        *(float4*)&Cp[(size_t)m * D + j0 + ty * 4] =
            make_float4(acc[i][0], acc[i][1], acc[i][2], acc[i][3]);
        *(float4*)&Cp[(size_t)m * D + j0 + 64 + ty * 4] =
            make_float4(acc[i][4], acc[i][5], acc[i][6], acc[i][7]);
    }
}

// K5: grad = 0.5 * (sum_z Gp / N - I)   (kappa = 0.5 collapses the formula)
__global__ __launch_bounds__(256) void k_grad(float* __restrict__ grad) {
    const int e = (blockIdx.x * 256 + threadIdx.x) * 4;  // 4 consecutive elems
    const int i = e / D, j = e % D;
    float4 s = make_float4(0.f, 0.f, 0.f, 0.f);
#pragma unroll
    for (int z = 0; z < KSPLIT; z++) {
        float4 v = *(const float4*)&g_Gp[(size_t)z * D * D + e];
        s.x += v.x; s.y += v.y; s.z += v.z; s.w += v.w;
    }
    const float invN = 1.0f / (float)NROWS;
    float4 o;
    o.x = 0.5f * (s.x * invN - (i == j + 0 ? 1.0f : 0.0f));
    o.y = 0.5f * (s.y * invN - (i == j + 1 ? 1.0f : 0.0f));
    o.z = 0.5f * (s.z * invN - (i == j + 2 ? 1.0f : 0.0f));
    o.w = 0.5f * (s.w * invN - (i == j + 3 ? 1.0f : 0.0f));
    *(float4*)&grad[e] = o;
}

// K6: per-row r = sum x^2, q = sum x^4 over xs
__global__ __launch_bounds__(256) void k_rowstats() {
    const int row = blockIdx.x;
    const float* p = g_xs + (size_t)row * D;
    float4 v = *(const float4*)&p[threadIdx.x * 4];
    float t0 = v.x * v.x, t1 = v.y * v.y, t2 = v.z * v.z, t3 = v.w * v.w;
    float r = t0 + t1 + t2 + t3;
    float q = t0 * t0 + t1 * t1 + t2 * t2 + t3 * t3;
#pragma unroll
    for (int o = 16; o > 0; o >>= 1) {
        r += __shfl_xor_sync(0xFFFFFFFFu, r, o);
        q += __shfl_xor_sync(0xFFFFFFFFu, q, o);
    }
    __shared__ float sr[8], sq[8];
    const int w = threadIdx.x >> 5;
    if ((threadIdx.x & 31) == 0) { sr[w] = r; sq[w] = q; }
    __syncthreads();
    if (threadIdx.x == 0) {
        float R = 0.f, Q = 0.f;
#pragma unroll
        for (int k = 0; k < 8; k++) { R += sr[k]; Q += sq[k]; }
        g_row_r[row] = R;
        g_row_q[row] = Q;
    }
}

// K7: losses.
//   sum(S) = sum_n r_n^2, trace(S) = sum_n q_n
//   corr  = (sum r^2 - sum q) / (N d^2)
//   whit  = (sum q - 2 sum r + N d) / (N d^2)
__global__ __launch_bounds__(256) void k_final(float* __restrict__ out2) {
    double sr = 0.0, sr2 = 0.0, sq = 0.0;
    for (int row = threadIdx.x; row < NROWS; row += 256) {
        double r = (double)g_row_r[row];
        double q = (double)g_row_q[row];
        sr += r; sr2 += r * r; sq += q;
    }
    __shared__ double sh[3][256];
    sh[0][threadIdx.x] = sr; sh[1][threadIdx.x] = sr2; sh[2][threadIdx.x] = sq;
    __syncthreads();
    for (int s = 128; s > 0; s >>= 1) {
        if (threadIdx.x < s) {
            sh[0][threadIdx.x] += sh[0][threadIdx.x + s];
            sh[1][threadIdx.x] += sh[1][threadIdx.x + s];
            sh[2][threadIdx.x] += sh[2][threadIdx.x + s];
        }
        __syncthreads();
    }
    if (threadIdx.x == 0) {
        const double denom = (double)NROWS * (double)D * (double)D;
        out2[0] = (float)((sh[1][0] - sh[2][0]) / denom);
        out2[1] = (float)((sh[2][0] - 2.0 * sh[0][0] + (double)NROWS * (double)D) / denom);
    }
}

extern "C" void kernel_launch(void* const* d_in, const int* in_sizes, int n_in,
                              void* d_out, int out_size) {
    const float* x    = (const float*)d_in[0];
    const float* W    = (const float*)d_in[1];
    const float* bias = (const float*)d_in[2];
    const float* dec  = (const float*)d_in[3];
    const int*   sidx = (const int*)d_in[4];

    float* out  = (float*)d_out;
    float* y    = out;                               // 32768*1024
    float* grad = out + (size_t)MROWS * D;           // 1024*1024
    float* scal = grad + (size_t)D * D;              // 2 scalars

    dim3 blk(256);
    k_prep_M   <<<dim3(D / BN, D / BM),            blk>>>(W, dec);
    k_y        <<<dim3(D / BN, MROWS / BM),        blk>>>(x, bias, y);
    k_xs       <<<dim3(D / BN, NROWS / BM),        blk>>>(x, dec, sidx);
    k_syrk_part<<<dim3(D / BN, D / BM, KSPLIT),    blk>>>();
    k_grad     <<<dim3((D * D / 4) / 256),         blk>>>(grad);
    k_rowstats <<<dim3(NROWS),                     blk>>>();
    k_final    <<<1,                               blk>>>(scal);
}

// round 3
// speedup vs baseline: 2.2065x; 2.2065x over previous
#include <cuda_runtime.h>
#include <stdint.h>

// Fixed problem shapes
#define D      1024
#define LSEQ   8192
#define NROWS  8192            // 4 * 2048 sampled rows
#define MROWS  32768           // 4 * 8192 output rows
#define KSPLIT 4
#define KCHUNK (NROWS / KSPLIT)

// Tensor-core GEMM tiling: 128x128 CTA tile, BK=16, 256 threads (8 warps 4x2),
// warp tile 32x64 via m16n8k8 tf32 mma.
#define BM 128
#define BN 128
#define BK 16
#define SSTR 128
#define STAGE_WORDS (BK * SSTR)

// Device-global scratch (no allocations allowed)
__device__ float g_M[(size_t)D * D];           // W @ decorr
__device__ float g_xs[(size_t)NROWS * D];      // gathered x @ decorr^T
__device__ float g_Gp[(size_t)KSPLIT * D * D]; // split-K partials of xs^T xs
__device__ float g_row_r[NROWS];
__device__ float g_row_q[NROWS];

__device__ __forceinline__ uint32_t f2tf(float f) {
    uint32_t u;
    asm("cvt.rna.tf32.f32 %0, %1;" : "=r"(u) : "f"(f));
    return u;
}

// XOR swizzle: conflict-free for mma fragment LDS, transpose STS, and uint4 STS.
__device__ __forceinline__ int swz(int k, int c) {
    return k * SSTR + (c ^ (((k ^ (k >> 3)) & 3) << 3));
}

__device__ __forceinline__ void mma8(float d[4], const uint32_t a[4], const uint32_t b[2]) {
    asm volatile(
        "mma.sync.aligned.m16n8k8.row.col.f32.tf32.tf32.f32 "
        "{%0,%1,%2,%3},{%4,%5,%6,%7},{%8,%9},{%0,%1,%2,%3};\n"
        : "+f"(d[0]), "+f"(d[1]), "+f"(d[2]), "+f"(d[3])
        : "r"(a[0]), "r"(a[1]), "r"(a[2]), "r"(a[3]), "r"(b[0]), "r"(b[1]));
}

// Transpose store: thread owns source row r, k-range [kh, kh+8)
__device__ __forceinline__ void sts_trans(uint32_t* s, int r, int kh, float4 v0, float4 v1) {
    s[swz(kh + 0, r)] = f2tf(v0.x);
    s[swz(kh + 1, r)] = f2tf(v0.y);
    s[swz(kh + 2, r)] = f2tf(v0.z);
    s[swz(kh + 3, r)] = f2tf(v0.w);
    s[swz(kh + 4, r)] = f2tf(v1.x);
    s[swz(kh + 5, r)] = f2tf(v1.y);
    s[swz(kh + 6, r)] = f2tf(v1.z);
    s[swz(kh + 7, r)] = f2tf(v1.w);
}

// Direct store: thread owns k-rows k1 and k1+8, 4 consecutive cols at c4*4
__device__ __forceinline__ void sts_direct(uint32_t* s, int k1, int c4, float4 v0, float4 v1) {
    uint4 u0 = make_uint4(f2tf(v0.x), f2tf(v0.y), f2tf(v0.z), f2tf(v0.w));
    uint4 u1 = make_uint4(f2tf(v1.x), f2tf(v1.y), f2tf(v1.z), f2tf(v1.w));
    int k2 = k1 + 8;
    *(uint4*)&s[k1 * SSTR + ((c4 * 4) ^ (((k1 ^ (k1 >> 3)) & 3) << 3))] = u0;
    *(uint4*)&s[k2 * SSTR + ((c4 * 4) ^ (((k2 ^ (k2 >> 3)) & 3) << 3))] = u1;
}

__device__ __forceinline__ void compute_stage(const uint32_t* sA, const uint32_t* sB,
                                              float (&acc)[2][8][4],
                                              int wm, int wn, int g, int tg) {
#pragma unroll
    for (int kk = 0; kk < BK; kk += 8) {
        uint32_t af[2][4], bf[8][2];
#pragma unroll
        for (int mt = 0; mt < 2; mt++) {
            int m = wm + mt * 16 + g;
            af[mt][0] = sA[swz(kk + tg,     m)];
            af[mt][1] = sA[swz(kk + tg,     m + 8)];
            af[mt][2] = sA[swz(kk + tg + 4, m)];
            af[mt][3] = sA[swz(kk + tg + 4, m + 8)];
        }
#pragma unroll
        for (int nt = 0; nt < 8; nt++) {
            int n = wn + nt * 8 + g;
            bf[nt][0] = sB[swz(kk + tg,     n)];
            bf[nt][1] = sB[swz(kk + tg + 4, n)];
        }
#pragma unroll
        for (int mt = 0; mt < 2; mt++)
#pragma unroll
            for (int nt = 0; nt < 8; nt++)
                mma8(acc[mt][nt], af[mt], bf[nt]);
    }
}

__device__ __forceinline__ void epilogue(float* C, int ldc, int m0, int n0,
                                         float (&acc)[2][8][4],
                                         int wm, int wn, int g, int tg,
                                         const float* bias) {
#pragma unroll
    for (int mt = 0; mt < 2; mt++) {
        int row = m0 + wm + mt * 16 + g;
#pragma unroll
        for (int nt = 0; nt < 8; nt++) {
            int col = n0 + wn + nt * 8 + tg * 2;
            float bx = 0.f, by = 0.f;
            if (bias) { bx = bias[col]; by = bias[col + 1]; }
            *(float2*)&C[(size_t)row * ldc + col] =
                make_float2(acc[mt][nt][0] + bx, acc[mt][nt][1] + by);
            *(float2*)&C[(size_t)(row + 8) * ldc + col] =
                make_float2(acc[mt][nt][2] + bx, acc[mt][nt][3] + by);
        }
    }
}

// ---------------------------------------------------------------------------
// K1: g_M = W @ dec   (A trans-load from W, B direct-load from dec)
// ---------------------------------------------------------------------------
__global__ __launch_bounds__(256, 2) void k_prep_M(const float* __restrict__ W,
                                                   const float* __restrict__ dec) {
    __shared__ uint32_t sA[2][STAGE_WORDS], sB[2][STAGE_WORDS];
    const int t = threadIdx.x;
    const int m0 = blockIdx.y * BM, n0 = blockIdx.x * BN;
    const int lane = t & 31, warp = t >> 5;
    const int g = lane >> 2, tg = lane & 3;
    const int wm = (warp & 3) * 32, wn = (warp >> 2) * 64;
    const int lr = t >> 1, kh = (t & 1) * 8;
    const int k1 = t >> 5, c4 = t & 31;
    const float* aptr = W + (size_t)(m0 + lr) * D + kh;
    const float* bptr = dec + (size_t)k1 * D + n0 + c4 * 4;
    float acc[2][8][4] = {};
    float4 a0 = *(const float4*)(aptr);
    float4 a1 = *(const float4*)(aptr + 4);
    float4 b0 = *(const float4*)(bptr);
    float4 b1 = *(const float4*)(bptr + (size_t)8 * D);
    sts_trans(sA[0], lr, kh, a0, a1);
    sts_direct(sB[0], k1, c4, b0, b1);
    __syncthreads();
    int cur = 0;
    const int S = D / BK;
    for (int s = 0; s < S; s++) {
        if (s + 1 < S) {
            size_t k0 = (size_t)(s + 1) * BK;
            a0 = *(const float4*)(aptr + k0);
            a1 = *(const float4*)(aptr + k0 + 4);
            b0 = *(const float4*)(bptr + k0 * D);
            b1 = *(const float4*)(bptr + (k0 + 8) * D);
        }
        compute_stage(sA[cur], sB[cur], acc, wm, wn, g, tg);
        if (s + 1 < S) {
            __syncthreads();
            sts_trans(sA[cur ^ 1], lr, kh, a0, a1);
            sts_direct(sB[cur ^ 1], k1, c4, b0, b1);
            __syncthreads();
            cur ^= 1;
        }
    }
    epilogue(g_M, D, m0, n0, acc, wm, wn, g, tg, nullptr);
}

// ---------------------------------------------------------------------------
// K2: y = x @ g_M^T + bias   (both trans-load, NT)
// ---------------------------------------------------------------------------
__global__ __launch_bounds__(256, 2) void k_y(const float* __restrict__ x,
                                              const float* __restrict__ bias,
                                              float* __restrict__ y) {
    __shared__ uint32_t sA[2][STAGE_WORDS], sB[2][STAGE_WORDS];
    const int t = threadIdx.x;
    const int m0 = blockIdx.y * BM, n0 = blockIdx.x * BN;
    const int lane = t & 31, warp = t >> 5;
    const int g = lane >> 2, tg = lane & 3;
    const int wm = (warp & 3) * 32, wn = (warp >> 2) * 64;
    const int lr = t >> 1, kh = (t & 1) * 8;
    const float* aptr = x + (size_t)(m0 + lr) * D + kh;
    const float* bptr = g_M + (size_t)(n0 + lr) * D + kh;
    float acc[2][8][4] = {};
    float4 a0 = *(const float4*)(aptr);
    float4 a1 = *(const float4*)(aptr + 4);
    float4 b0 = *(const float4*)(bptr);
    float4 b1 = *(const float4*)(bptr + 4);
    sts_trans(sA[0], lr, kh, a0, a1);
    sts_trans(sB[0], lr, kh, b0, b1);
    __syncthreads();
    int cur = 0;
    const int S = D / BK;
    for (int s = 0; s < S; s++) {
        if (s + 1 < S) {
            int k0 = (s + 1) * BK;
            a0 = *(const float4*)(aptr + k0);
            a1 = *(const float4*)(aptr + k0 + 4);
            b0 = *(const float4*)(bptr + k0);
            b1 = *(const float4*)(bptr + k0 + 4);
        }
        compute_stage(sA[cur], sB[cur], acc, wm, wn, g, tg);
        if (s + 1 < S) {
            __syncthreads();
            sts_trans(sA[cur ^ 1], lr, kh, a0, a1);
            sts_trans(sB[cur ^ 1], lr, kh, b0, b1);
            __syncthreads();
            cur ^= 1;
        }
    }
    epilogue(y, D, m0, n0, acc, wm, wn, g, tg, bias);
}

// ---------------------------------------------------------------------------
// K3: g_xs = gather(x, sidx) @ dec^T   (A trans-load gathered, B trans-load)
// ---------------------------------------------------------------------------
__global__ __launch_bounds__(256, 2) void k_xs(const float* __restrict__ x,
                                               const float* __restrict__ dec,
                                               const int* __restrict__ sidx) {
    __shared__ uint32_t sA[2][STAGE_WORDS], sB[2][STAGE_WORDS];
    const int t = threadIdx.x;
    const int m0 = blockIdx.y * BM, n0 = blockIdx.x * BN;
    const int lane = t & 31, warp = t >> 5;
    const int g = lane >> 2, tg = lane & 3;
    const int wm = (warp & 3) * 32, wn = (warp >> 2) * 64;
    const int lr = t >> 1, kh = (t & 1) * 8;
    const int gr = m0 + lr;
    const int bidx = gr >> 11;
    const int tok = sidx[gr];
    const float* aptr = x + ((size_t)bidx * LSEQ + (size_t)tok) * D + kh;
    const float* bptr = dec + (size_t)(n0 + lr) * D + kh;
    float acc[2][8][4] = {};
    float4 a0 = *(const float4*)(aptr);
    float4 a1 = *(const float4*)(aptr + 4);
    float4 b0 = *(const float4*)(bptr);
    float4 b1 = *(const float4*)(bptr + 4);
    sts_trans(sA[0], lr, kh, a0, a1);
    sts_trans(sB[0], lr, kh, b0, b1);
    __syncthreads();
    int cur = 0;
    const int S = D / BK;
    for (int s = 0; s < S; s++) {
        if (s + 1 < S) {
            int k0 = (s + 1) * BK;
            a0 = *(const float4*)(aptr + k0);
            a1 = *(const float4*)(aptr + k0 + 4);
            b0 = *(const float4*)(bptr + k0);
            b1 = *(const float4*)(bptr + k0 + 4);
        }
        compute_stage(sA[cur], sB[cur], acc, wm, wn, g, tg);
        if (s + 1 < S) {
            __syncthreads();
            sts_trans(sA[cur ^ 1], lr, kh, a0, a1);
            sts_trans(sB[cur ^ 1], lr, kh, b0, b1);
            __syncthreads();
            cur ^= 1;
        }
    }
    epilogue(g_xs, D, m0, n0, acc, wm, wn, g, tg, nullptr);
}

// ---------------------------------------------------------------------------
// K4: split-K SYRK partials: g_Gp[z] = xs[zK:(z+1)K]^T @ xs[...]  (both direct)
// ---------------------------------------------------------------------------
__global__ __launch_bounds__(256, 2) void k_syrk() {
    __shared__ uint32_t sA[2][STAGE_WORDS], sB[2][STAGE_WORDS];
    const int t = threadIdx.x;
    const int i0 = blockIdx.y * BM, j0 = blockIdx.x * BN;
    const int lane = t & 31, warp = t >> 5;
    const int g = lane >> 2, tg = lane & 3;
    const int wm = (warp & 3) * 32, wn = (warp >> 2) * 64;
    const int k1 = t >> 5, c4 = t & 31;
    const size_t zoff = (size_t)blockIdx.z * KCHUNK;
    const float* aptr = g_xs + (zoff + k1) * D + i0 + c4 * 4;
    const float* bptr = g_xs + (zoff + k1) * D + j0 + c4 * 4;
    float acc[2][8][4] = {};
    float4 a0 = *(const float4*)(aptr);
    float4 a1 = *(const float4*)(aptr + (size_t)8 * D);
    float4 b0 = *(const float4*)(bptr);
    float4 b1 = *(const float4*)(bptr + (size_t)8 * D);
    sts_direct(sA[0], k1, c4, a0, a1);
    sts_direct(sB[0], k1, c4, b0, b1);
    __syncthreads();
    int cur = 0;
    const int S = KCHUNK / BK;
    for (int s = 0; s < S; s++) {
        if (s + 1 < S) {
            size_t k0 = (size_t)(s + 1) * BK;
            a0 = *(const float4*)(aptr + k0 * D);
            a1 = *(const float4*)(aptr + (k0 + 8) * D);
            b0 = *(const float4*)(bptr + k0 * D);
            b1 = *(const float4*)(bptr + (k0 + 8) * D);
        }
        compute_stage(sA[cur], sB[cur], acc, wm, wn, g, tg);
        if (s + 1 < S) {
            __syncthreads();
            sts_direct(sA[cur ^ 1], k1, c4, a0, a1);
            sts_direct(sB[cur ^ 1], k1, c4, b0, b1);
            __syncthreads();
            cur ^= 1;
        }
    }
    epilogue(g_Gp + (size_t)blockIdx.z * D * D, D, i0, j0, acc, wm, wn, g, tg, nullptr);
}

// K5: grad = 0.5 * (sum_z Gp / N - I)    (kappa = 0.5 collapses the formula)
__global__ __launch_bounds__(256) void k_grad(float* __restrict__ grad) {
    const int e = (blockIdx.x * 256 + threadIdx.x) * 4;
    const int i = e / D, j = e % D;
    float4 s = make_float4(0.f, 0.f, 0.f, 0.f);
#pragma unroll
    for (int z = 0; z < KSPLIT; z++) {
        float4 v = *(const float4*)&g_Gp[(size_t)z * D * D + e];
        s.x += v.x; s.y += v.y; s.z += v.z; s.w += v.w;
    }
    const float invN = 1.0f / (float)NROWS;
    float4 o;
    o.x = 0.5f * (s.x * invN - (i == j + 0 ? 1.0f : 0.0f));
    o.y = 0.5f * (s.y * invN - (i == j + 1 ? 1.0f : 0.0f));
    o.z = 0.5f * (s.z * invN - (i == j + 2 ? 1.0f : 0.0f));
    o.w = 0.5f * (s.w * invN - (i == j + 3 ? 1.0f : 0.0f));
    *(float4*)&grad[e] = o;
}

// K6: per-row r = sum x^2, q = sum x^4 over xs
__global__ __launch_bounds__(256) void k_rowstats() {
    const int row = blockIdx.x;
    const float* p = g_xs + (size_t)row * D;
    float4 v = *(const float4*)&p[threadIdx.x * 4];
    float t0 = v.x * v.x, t1 = v.y * v.y, t2 = v.z * v.z, t3 = v.w * v.w;
    float r = t0 + t1 + t2 + t3;
    float q = t0 * t0 + t1 * t1 + t2 * t2 + t3 * t3;
#pragma unroll
    for (int o = 16; o > 0; o >>= 1) {
        r += __shfl_xor_sync(0xFFFFFFFFu, r, o);
        q += __shfl_xor_sync(0xFFFFFFFFu, q, o);
    }
    __shared__ float sr[8], sq[8];
    const int w = threadIdx.x >> 5;
    if ((threadIdx.x & 31) == 0) { sr[w] = r; sq[w] = q; }
    __syncthreads();
    if (threadIdx.x == 0) {
        float R = 0.f, Q = 0.f;
#pragma unroll
        for (int k = 0; k < 8; k++) { R += sr[k]; Q += sq[k]; }
        g_row_r[row] = R;
        g_row_q[row] = Q;
    }
}

// K7: losses from row stats
__global__ __launch_bounds__(256) void k_final(float* __restrict__ out2) {
    double sr = 0.0, sr2 = 0.0, sq = 0.0;
    for (int row = threadIdx.x; row < NROWS; row += 256) {
        double r = (double)g_row_r[row];
        double q = (double)g_row_q[row];
        sr += r; sr2 += r * r; sq += q;
    }
    __shared__ double sh[3][256];
    sh[0][threadIdx.x] = sr; sh[1][threadIdx.x] = sr2; sh[2][threadIdx.x] = sq;
    __syncthreads();
    for (int s = 128; s > 0; s >>= 1) {
        if (threadIdx.x < s) {
            sh[0][threadIdx.x] += sh[0][threadIdx.x + s];
            sh[1][threadIdx.x] += sh[1][threadIdx.x + s];
            sh[2][threadIdx.x] += sh[2][threadIdx.x + s];
        }
        __syncthreads();
    }
    if (threadIdx.x == 0) {
        const double denom = (double)NROWS * (double)D * (double)D;
        out2[0] = (float)((sh[1][0] - sh[2][0]) / denom);
        out2[1] = (float)((sh[2][0] - 2.0 * sh[0][0] + (double)NROWS * (double)D) / denom);
    }
}

extern "C" void kernel_launch(void* const* d_in, const int* in_sizes, int n_in,
                              void* d_out, int out_size) {
    const float* x    = (const float*)d_in[0];
    const float* W    = (const float*)d_in[1];
    const float* bias = (const float*)d_in[2];
    const float* dec  = (const float*)d_in[3];
    const int*   sidx = (const int*)d_in[4];

    float* out  = (float*)d_out;
    float* y    = out;
    float* grad = out + (size_t)MROWS * D;
    float* scal = grad + (size_t)D * D;

    dim3 blk(256);
    k_prep_M <<<dim3(D / BN, D / BM),            blk>>>(W, dec);
    k_y      <<<dim3(D / BN, MROWS / BM),        blk>>>(x, bias, y);
    k_xs     <<<dim3(D / BN, NROWS / BM),        blk>>>(x, dec, sidx);
    k_syrk   <<<dim3(D / BN, D / BM, KSPLIT),    blk>>>();
    k_grad   <<<dim3((D * D / 4) / 256),         blk>>>(grad);
    k_rowstats<<<dim3(NROWS),                    blk>>>();
    k_final  <<<1,                               blk>>>(scal);
}